// round 6
// baseline (speedup 1.0000x reference)
#include <cuda_runtime.h>
#include <cstdint>

#define SEQ 4096
#define HD 64
#define NBATCH 4
#define TQ 128
#define TN 64
#define NIT 64
#define PAD 68
#define NTH 256
#define CEXP 0.18033688011112042f  // log2(e)/temperature(8)

// smem float offsets
#define O_QP 0        // Q (prologue) then P buffer 0: 128*68 = 8704
#define O_P1 8704     // P buffer 1: 8704
#define O_K 17408     // 4 ring buffers of 64*68 = 4352
#define O_V 34816     // 4 ring buffers of 4352
#define O_RS 52224    // 128 rowsums
#define SMEM_BYTES ((52224 + 128) * 4)

__device__ __forceinline__ uint32_t f2tf(float x) {
    uint32_t u;
    asm("cvt.rna.tf32.f32 %0, %1;" : "=r"(u) : "f"(x));
    return u;
}

__device__ __forceinline__ void mma8(float c[4], const uint32_t a[4], const uint32_t b[2]) {
    asm volatile(
        "mma.sync.aligned.m16n8k8.row.col.f32.tf32.tf32.f32 "
        "{%0,%1,%2,%3}, {%4,%5,%6,%7}, {%8,%9}, {%0,%1,%2,%3};\n"
        : "+f"(c[0]), "+f"(c[1]), "+f"(c[2]), "+f"(c[3])
        : "r"(a[0]), "r"(a[1]), "r"(a[2]), "r"(a[3]), "r"(b[0]), "r"(b[1]));
}

__global__ void __launch_bounds__(NTH, 1)
attn_fused(const float* __restrict__ Q, const float* __restrict__ K,
           const float* __restrict__ V, float* __restrict__ outp,
           float* __restrict__ attnp) {
    extern __shared__ float sm[];
    const int tid = threadIdx.x, w = tid >> 5, lane = tid & 31;
    const int g = lane >> 2, tg = lane & 3;
    const int b = blockIdx.x >> 5;
    const int q0 = (blockIdx.x & 31) << 7;  // 128-row q tile
    const int wq = (w >> 1) * 32, wn = (w & 1) * 32;

    const float* Qb = Q + ((size_t)b * SEQ + q0) * HD;
    const float* Kb = K + (size_t)b * SEQ * HD;
    const float* Vb = V + (size_t)b * SEQ * HD;

    float* QP = sm + O_QP;
    float* RS = sm + O_RS;

    if (tid < TQ) RS[tid] = 0.f;

    // ---- stage Q tile (128x64, tf32-rounded, PAD layout) ----
#pragma unroll
    for (int t = 0; t < 8; ++t) {
        int idx = tid + t * NTH;
        int r = idx >> 4, c4 = (idx & 15) << 2;
        float4 v = *reinterpret_cast<const float4*>(Qb + r * HD + c4);
        *reinterpret_cast<uint4*>(QP + r * PAD + c4) =
            make_uint4(f2tf(v.x), f2tf(v.y), f2tf(v.z), f2tf(v.w));
    }
    __syncthreads();

    // ---- hoist Q fragments (loop-invariant) ----
    uint32_t qf[8][2][4];
#pragma unroll
    for (int kk = 0; kk < 8; ++kk) {
        const int k0 = kk * 8;
#pragma unroll
        for (int i = 0; i < 2; ++i) {
            const int r = wq + i * 16 + g;
            qf[kk][i][0] = __float_as_uint(QP[r * PAD + k0 + tg]);
            qf[kk][i][1] = __float_as_uint(QP[(r + 8) * PAD + k0 + tg]);
            qf[kk][i][2] = __float_as_uint(QP[r * PAD + k0 + tg + 4]);
            qf[kk][i][3] = __float_as_uint(QP[(r + 8) * PAD + k0 + tg + 4]);
        }
    }
    __syncthreads();  // all warps hoisted Q before P overwrites QP (phase B)

    float4 kr[4], vr[4];
    auto ldg64 = [&](const float* src, int n0, float4 rr[4]) {
#pragma unroll
        for (int t = 0; t < 4; ++t) {
            int idx = tid + t * NTH;
            int r = idx >> 4, c4 = (idx & 15) << 2;
            rr[t] = *reinterpret_cast<const float4*>(src + (size_t)(n0 + r) * HD + c4);
        }
    };
    auto sts64 = [&](float* dst, const float4 rr[4]) {
#pragma unroll
        for (int t = 0; t < 4; ++t) {
            int idx = tid + t * NTH;
            int r = idx >> 4, c4 = (idx & 15) << 2;
            *reinterpret_cast<uint4*>(dst + r * PAD + c4) =
                make_uint4(f2tf(rr[t].x), f2tf(rr[t].y), f2tf(rr[t].z), f2tf(rr[t].w));
        }
    };
    auto qk_issue = [&](float (&c)[2][4][4], const float* Ks) {
#pragma unroll
        for (int kk = 0; kk < 8; ++kk) {
            const int k0 = kk * 8;
#pragma unroll
            for (int j = 0; j < 4; ++j) {
                const int n = wn + j * 8 + g;
                uint32_t bb[2] = {__float_as_uint(Ks[n * PAD + k0 + tg]),
                                  __float_as_uint(Ks[n * PAD + k0 + tg + 4])};
                mma8(c[0][j], qf[kk][0], bb);
                mma8(c[1][j], qf[kk][1], bb);
            }
        }
    };
    auto zero_acc = [&](float (&c)[2][4][4]) {
#pragma unroll
        for (int i = 0; i < 2; ++i)
#pragma unroll
            for (int j = 0; j < 4; ++j)
#pragma unroll
                for (int t = 0; t < 4; ++t) c[i][j][t] = 0.f;
    };

    float rsum[2][2] = {{0.f, 0.f}, {0.f, 0.f}};
    float cA[2][4][4] = {}, cB[2][4][4] = {};

    // ================= Phase A: rowsums of exp (1 barrier/iter) =================
    {
        ldg64(Kb, 0, kr);
        sts64(sm + O_K + 0 * 4352, kr);
        ldg64(Kb, TN, kr);
        __syncthreads();
        qk_issue(cA, sm + O_K + 0 * 4352);

        auto bodyA = [&](int it, float (&cc)[2][4][4], float (&cn)[2][4][4]) {
            if (it + 1 < NIT) sts64(sm + O_K + ((it + 1) & 3) * 4352, kr);
            __syncthreads();
            if (it + 1 < NIT) {
                zero_acc(cn);
                qk_issue(cn, sm + O_K + ((it + 1) & 3) * 4352);
            }
            if (it + 2 < NIT) ldg64(Kb, (it + 2) * TN, kr);
#pragma unroll
            for (int i = 0; i < 2; ++i)
#pragma unroll
                for (int j = 0; j < 4; ++j) {
                    rsum[i][0] += exp2f(cc[i][j][0] * CEXP) + exp2f(cc[i][j][1] * CEXP);
                    rsum[i][1] += exp2f(cc[i][j][2] * CEXP) + exp2f(cc[i][j][3] * CEXP);
                }
        };
        for (int it = 0; it < NIT; it += 2) {
            bodyA(it, cA, cB);
            bodyA(it + 1, cB, cA);
        }
    }
#pragma unroll
    for (int i = 0; i < 2; ++i)
#pragma unroll
        for (int h = 0; h < 2; ++h) {
            float v = rsum[i][h];
            v += __shfl_xor_sync(0xffffffffu, v, 1);
            v += __shfl_xor_sync(0xffffffffu, v, 2);
            if (tg == 0) atomicAdd(&RS[wq + i * 16 + h * 8 + g], v);
        }
    __syncthreads();
    float lr[2][2];  // -log2(rowsum), folded into exp2
#pragma unroll
    for (int i = 0; i < 2; ++i)
#pragma unroll
        for (int h = 0; h < 2; ++h) lr[i][h] = -log2f(RS[wq + i * 16 + h * 8 + g]);
    __syncthreads();

    // ================= Phase B: attn + AV (1 barrier/iter) =================
    float o[2][4][4] = {};
    {
        ldg64(Kb, 0, kr);
        ldg64(Vb, 0, vr);
        sts64(sm + O_K + 0 * 4352, kr);
        sts64(sm + O_V + 0 * 4352, vr);
        ldg64(Kb, TN, kr);
        ldg64(Vb, TN, vr);
        __syncthreads();
        zero_acc(cA);
        qk_issue(cA, sm + O_K + 0 * 4352);

        auto bodyB = [&](int it, float (&cc)[2][4][4], float (&cn)[2][4][4]) {
            const int n0 = it * TN;
            // --- pre-barrier: stage next K/V, exp+attn STG, P store ---
            if (it + 1 < NIT) {
                sts64(sm + O_K + ((it + 1) & 3) * 4352, kr);
                sts64(sm + O_V + ((it + 1) & 3) * 4352, vr);
            }
            float* Pb = sm + ((it & 1) ? O_P1 : O_QP);
#pragma unroll
            for (int i = 0; i < 2; ++i) {
                const int row = q0 + wq + i * 16 + g;
                float* ar = attnp + ((size_t)b * SEQ + row) * SEQ + n0 + wn;
                const int r = wq + i * 16 + g;
#pragma unroll
                for (int j = 0; j < 4; ++j) {
                    cc[i][j][0] = exp2f(fmaf(cc[i][j][0], CEXP, lr[i][0]));
                    cc[i][j][1] = exp2f(fmaf(cc[i][j][1], CEXP, lr[i][0]));
                    cc[i][j][2] = exp2f(fmaf(cc[i][j][2], CEXP, lr[i][1]));
                    cc[i][j][3] = exp2f(fmaf(cc[i][j][3], CEXP, lr[i][1]));
                    __stcs(reinterpret_cast<float2*>(ar + j * 8 + 2 * tg),
                           make_float2(cc[i][j][0], cc[i][j][1]));
                    __stcs(reinterpret_cast<float2*>(ar + (size_t)8 * SEQ + j * 8 + 2 * tg),
                           make_float2(cc[i][j][2], cc[i][j][3]));
                    const int col = wn + j * 8 + 2 * tg;
                    *reinterpret_cast<uint2*>(&Pb[r * PAD + col]) =
                        make_uint2(f2tf(cc[i][j][0]), f2tf(cc[i][j][1]));
                    *reinterpret_cast<uint2*>(&Pb[(r + 8) * PAD + col]) =
                        make_uint2(f2tf(cc[i][j][2]), f2tf(cc[i][j][3]));
                }
            }
            __syncthreads();  // P + next K/V visible to all warps
            // --- post-barrier: next QK, this AV, prefetch ---
            if (it + 1 < NIT) {
                zero_acc(cn);
                qk_issue(cn, sm + O_K + ((it + 1) & 3) * 4352);
            }
            const float* Vs = sm + O_V + (it & 3) * 4352;
#pragma unroll
            for (int kk = 0; kk < 8; ++kk) {
                const int k0 = kk * 8;
                uint32_t a[2][4];
#pragma unroll
                for (int i = 0; i < 2; ++i) {
                    const int r = wq + i * 16 + g;
                    a[i][0] = __float_as_uint(Pb[r * PAD + k0 + tg]);
                    a[i][1] = __float_as_uint(Pb[(r + 8) * PAD + k0 + tg]);
                    a[i][2] = __float_as_uint(Pb[r * PAD + k0 + tg + 4]);
                    a[i][3] = __float_as_uint(Pb[(r + 8) * PAD + k0 + tg + 4]);
                }
#pragma unroll
                for (int j = 0; j < 4; ++j) {
                    uint32_t bb[2] = {
                        __float_as_uint(Vs[(k0 + tg) * PAD + wn + j * 8 + g]),
                        __float_as_uint(Vs[(k0 + tg + 4) * PAD + wn + j * 8 + g])};
                    mma8(o[0][j], a[0], bb);
                    mma8(o[1][j], a[1], bb);
                }
            }
            if (it + 2 < NIT) {
                ldg64(Kb, (it + 2) * TN, kr);
                ldg64(Vb, (it + 2) * TN, vr);
            }
        };
        for (int it = 0; it < NIT; it += 2) {
            bodyB(it, cA, cB);
            bodyB(it + 1, cB, cA);
        }
    }

    // ---- epilogue: write out [B,S,64] ----
#pragma unroll
    for (int i = 0; i < 2; ++i) {
        const int row = q0 + wq + i * 16 + g;
        float* orow = outp + ((size_t)b * SEQ + row) * HD;
#pragma unroll
        for (int j = 0; j < 4; ++j) {
            const int col = wn + j * 8 + 2 * tg;
            *reinterpret_cast<float2*>(orow + col) = make_float2(o[i][j][0], o[i][j][1]);
            *reinterpret_cast<float2*>(orow + 8 * HD + col) =
                make_float2(o[i][j][2], o[i][j][3]);
        }
    }
}

extern "C" void kernel_launch(void* const* d_in, const int* in_sizes, int n_in,
                              void* d_out, int out_size) {
    const float* q = (const float*)d_in[0];
    const float* k = (const float*)d_in[1];
    const float* v = (const float*)d_in[2];
    float* outp = (float*)d_out;
    float* attnp = outp + (size_t)NBATCH * SEQ * HD;

    cudaFuncSetAttribute(attn_fused, cudaFuncAttributeMaxDynamicSharedMemorySize,
                         SMEM_BYTES);
    attn_fused<<<NBATCH * 32, NTH, SMEM_BYTES>>>(q, k, v, outp, attnp);
}

// round 7
// speedup vs baseline: 1.5520x; 1.5520x over previous
#include <cuda_runtime.h>
#include <cuda_fp16.h>
#include <cstdint>

#define SEQ 4096
#define HD 64
#define NBATCH 4
#define TQ 128
#define TN 64
#define NIT 64
#define PADH 72   // halves per smem row (144B): conflict-free ldmatrix + STS
#define NTH 256
#define CEXP 0.18033688011112042f  // log2(e)/temperature(8)

// smem HALF-index offsets
#define H_P0 0                // 128*72 halves (Q staged here in prologue, then P buf 0)
#define H_P1 9216             // P buf 1
#define H_K 18432             // 4 rings of 64*72 = 4608 halves
#define H_V 36864             // 4 rings of 4608
#define H_TOT 55296
#define SMEM_BYTES (H_TOT * 2 + 128 * 4)

__device__ __forceinline__ uint32_t f2h2(float x, float y) {
    __half2 h = __floats2half2_rn(x, y);
    return *reinterpret_cast<uint32_t*>(&h);
}

__device__ __forceinline__ void ldsm4(uint32_t& r0, uint32_t& r1, uint32_t& r2,
                                      uint32_t& r3, uint32_t addr) {
    asm volatile("ldmatrix.sync.aligned.m8n8.x4.shared.b16 {%0,%1,%2,%3}, [%4];"
                 : "=r"(r0), "=r"(r1), "=r"(r2), "=r"(r3) : "r"(addr));
}
__device__ __forceinline__ void ldsm4t(uint32_t& r0, uint32_t& r1, uint32_t& r2,
                                       uint32_t& r3, uint32_t addr) {
    asm volatile("ldmatrix.sync.aligned.m8n8.x4.trans.shared.b16 {%0,%1,%2,%3}, [%4];"
                 : "=r"(r0), "=r"(r1), "=r"(r2), "=r"(r3) : "r"(addr));
}
__device__ __forceinline__ void mma16(float c[4], const uint32_t a[4], uint32_t b0,
                                      uint32_t b1) {
    asm volatile(
        "mma.sync.aligned.m16n8k16.row.col.f32.f16.f16.f32 "
        "{%0,%1,%2,%3}, {%4,%5,%6,%7}, {%8,%9}, {%0,%1,%2,%3};\n"
        : "+f"(c[0]), "+f"(c[1]), "+f"(c[2]), "+f"(c[3])
        : "r"(a[0]), "r"(a[1]), "r"(a[2]), "r"(a[3]), "r"(b0), "r"(b1));
}

__global__ void __launch_bounds__(NTH, 1)
attn_fused(const float* __restrict__ Q, const float* __restrict__ K,
           const float* __restrict__ V, float* __restrict__ outp,
           float* __restrict__ attnp) {
    extern __shared__ __half sh[];
    float* RS = reinterpret_cast<float*>(sh + H_TOT);
    const uint32_t smb = (uint32_t)__cvta_generic_to_shared(sh);

    const int tid = threadIdx.x, w = tid >> 5, lane = tid & 31;
    const int g = lane >> 2, tg = lane & 3;
    const int lr3 = lane & 7, b3 = (lane >> 3) & 1, b4 = (lane >> 4) & 1;
    const int b = blockIdx.x >> 5;
    const int q0 = (blockIdx.x & 31) << 7;
    const int wq = (w >> 1) * 32, wn = (w & 1) * 32;

    // per-thread ldmatrix address components (bytes)
    const uint32_t kq_off = (uint32_t)(wn + b4 * 8 + lr3) * 144u + (uint32_t)b3 * 16u;
    const uint32_t pa_off = (uint32_t)(b3 * 8 + lr3) * 144u + (uint32_t)b4 * 16u;
    const uint32_t va_off = (uint32_t)(b3 * 8 + lr3) * 144u + (uint32_t)b4 * 16u +
                            (uint32_t)wn * 2u;

    const float* Qb = Q + ((size_t)b * SEQ + q0) * HD;
    const float* Kb = K + (size_t)b * SEQ * HD;
    const float* Vb = V + (size_t)b * SEQ * HD;

    if (tid < TQ) RS[tid] = 0.f;

    // ---- stage Q tile (128x64 fp16) into P0 region ----
#pragma unroll
    for (int t = 0; t < 8; ++t) {
        int idx = tid + t * NTH;
        int r = idx >> 4, c4 = (idx & 15) << 2;
        float4 v = *reinterpret_cast<const float4*>(Qb + r * HD + c4);
        *reinterpret_cast<uint2*>(&sh[H_P0 + r * PADH + c4]) =
            make_uint2(f2h2(v.x, v.y), f2h2(v.z, v.w));
    }
    __syncthreads();

    // ---- hoist Q fragments via ldmatrix (loop-invariant) ----
    uint32_t qf[4][2][4];
#pragma unroll
    for (int kk = 0; kk < 4; ++kk)
#pragma unroll
        for (int i = 0; i < 2; ++i)
            ldsm4(qf[kk][i][0], qf[kk][i][1], qf[kk][i][2], qf[kk][i][3],
                  smb + (uint32_t)(wq + i * 16) * 144u + pa_off + kk * 32u);
    __syncthreads();  // Q region dead; P may overwrite later

    float4 kr[4], vr[4];
    auto ldg64 = [&](const float* src, int n0, float4 rr[4]) {
#pragma unroll
        for (int t = 0; t < 4; ++t) {
            int idx = tid + t * NTH;
            int r = idx >> 4, c4 = (idx & 15) << 2;
            rr[t] = *reinterpret_cast<const float4*>(src + (size_t)(n0 + r) * HD + c4);
        }
    };
    auto sts_h = [&](uint32_t hbase, const float4 rr[4]) {
#pragma unroll
        for (int t = 0; t < 4; ++t) {
            int idx = tid + t * NTH;
            int r = idx >> 4, c4 = (idx & 15) << 2;
            *reinterpret_cast<uint2*>(&sh[hbase + r * PADH + c4]) =
                make_uint2(f2h2(rr[t].x, rr[t].y), f2h2(rr[t].z, rr[t].w));
        }
    };
    auto qk_issue = [&](float (&c)[2][4][4], uint32_t kbuf) {
#pragma unroll
        for (int kk = 0; kk < 4; ++kk) {
#pragma unroll
            for (int j2 = 0; j2 < 4; j2 += 2) {
                uint32_t b0, b1, b2_, b3_;
                ldsm4(b0, b1, b2_, b3_, kbuf + kq_off + (uint32_t)j2 * 1152u + kk * 32u);
                mma16(c[0][j2], qf[kk][0], b0, b1);
                mma16(c[1][j2], qf[kk][1], b0, b1);
                mma16(c[0][j2 + 1], qf[kk][0], b2_, b3_);
                mma16(c[1][j2 + 1], qf[kk][1], b2_, b3_);
            }
        }
    };
    auto zero_acc = [&](float (&c)[2][4][4]) {
#pragma unroll
        for (int i = 0; i < 2; ++i)
#pragma unroll
            for (int j = 0; j < 4; ++j)
#pragma unroll
                for (int t = 0; t < 4; ++t) c[i][j][t] = 0.f;
    };

    const uint32_t kB[4] = {smb + 2u * (H_K + 0 * 4608), smb + 2u * (H_K + 1 * 4608),
                            smb + 2u * (H_K + 2 * 4608), smb + 2u * (H_K + 3 * 4608)};
    const uint32_t vB[4] = {smb + 2u * (H_V + 0 * 4608), smb + 2u * (H_V + 1 * 4608),
                            smb + 2u * (H_V + 2 * 4608), smb + 2u * (H_V + 3 * 4608)};
    const uint32_t kH[4] = {H_K + 0 * 4608, H_K + 1 * 4608, H_K + 2 * 4608, H_K + 3 * 4608};
    const uint32_t vH[4] = {H_V + 0 * 4608, H_V + 1 * 4608, H_V + 2 * 4608, H_V + 3 * 4608};

    float rsum[2][2] = {{0.f, 0.f}, {0.f, 0.f}};
    float cA[2][4][4] = {}, cB_[2][4][4] = {};

    // ================= Phase A: rowsums of exp =================
    {
        ldg64(Kb, 0, kr);
        sts_h(kH[0], kr);
        ldg64(Kb, TN, kr);
        __syncthreads();
        qk_issue(cA, kB[0]);

        auto bodyA = [&](int it, float (&cc)[2][4][4], float (&cn)[2][4][4]) {
            if (it + 1 < NIT) sts_h(kH[(it + 1) & 3], kr);
            __syncthreads();
            if (it + 1 < NIT) {
                zero_acc(cn);
                qk_issue(cn, kB[(it + 1) & 3]);
            }
            if (it + 2 < NIT) ldg64(Kb, (it + 2) * TN, kr);
#pragma unroll
            for (int i = 0; i < 2; ++i)
#pragma unroll
                for (int j = 0; j < 4; ++j) {
                    rsum[i][0] += exp2f(cc[i][j][0] * CEXP) + exp2f(cc[i][j][1] * CEXP);
                    rsum[i][1] += exp2f(cc[i][j][2] * CEXP) + exp2f(cc[i][j][3] * CEXP);
                }
        };
        for (int it = 0; it < NIT; it += 2) {
            bodyA(it, cA, cB_);
            bodyA(it + 1, cB_, cA);
        }
    }
#pragma unroll
    for (int i = 0; i < 2; ++i)
#pragma unroll
        for (int h = 0; h < 2; ++h) {
            float v = rsum[i][h];
            v += __shfl_xor_sync(0xffffffffu, v, 1);
            v += __shfl_xor_sync(0xffffffffu, v, 2);
            if (tg == 0) atomicAdd(&RS[wq + i * 16 + h * 8 + g], v);
        }
    __syncthreads();
    float lr[2][2];
#pragma unroll
    for (int i = 0; i < 2; ++i)
#pragma unroll
        for (int h = 0; h < 2; ++h) lr[i][h] = -log2f(RS[wq + i * 16 + h * 8 + g]);
    __syncthreads();

    // ================= Phase B: attn + AV =================
    float o[2][4][4] = {};
    {
        ldg64(Kb, 0, kr);
        ldg64(Vb, 0, vr);
        sts_h(kH[0], kr);
        sts_h(vH[0], vr);
        ldg64(Kb, TN, kr);
        ldg64(Vb, TN, vr);
        __syncthreads();
        zero_acc(cA);
        qk_issue(cA, kB[0]);

        auto bodyB = [&](int it, float (&cc)[2][4][4], float (&cn)[2][4][4]) {
            const int n0 = it * TN;
            // --- pre-barrier: stage next K/V, exp + attn STG, P(fp16) STS ---
            if (it + 1 < NIT) {
                sts_h(kH[(it + 1) & 3], kr);
                sts_h(vH[(it + 1) & 3], vr);
            }
            const uint32_t pH = (it & 1) ? H_P1 : H_P0;
#pragma unroll
            for (int i = 0; i < 2; ++i) {
                const int row = q0 + wq + i * 16 + g;
                float* ar = attnp + ((size_t)b * SEQ + row) * SEQ + n0 + wn;
                const int r = wq + i * 16 + g;
#pragma unroll
                for (int j = 0; j < 4; ++j) {
                    cc[i][j][0] = exp2f(fmaf(cc[i][j][0], CEXP, lr[i][0]));
                    cc[i][j][1] = exp2f(fmaf(cc[i][j][1], CEXP, lr[i][0]));
                    cc[i][j][2] = exp2f(fmaf(cc[i][j][2], CEXP, lr[i][1]));
                    cc[i][j][3] = exp2f(fmaf(cc[i][j][3], CEXP, lr[i][1]));
                    __stcs(reinterpret_cast<float2*>(ar + j * 8 + 2 * tg),
                           make_float2(cc[i][j][0], cc[i][j][1]));
                    __stcs(reinterpret_cast<float2*>(ar + (size_t)8 * SEQ + j * 8 + 2 * tg),
                           make_float2(cc[i][j][2], cc[i][j][3]));
                    const int col = wn + j * 8 + 2 * tg;
                    *reinterpret_cast<uint32_t*>(&sh[pH + r * PADH + col]) =
                        f2h2(cc[i][j][0], cc[i][j][1]);
                    *reinterpret_cast<uint32_t*>(&sh[pH + (r + 8) * PADH + col]) =
                        f2h2(cc[i][j][2], cc[i][j][3]);
                }
            }
            __syncthreads();
            // --- post-barrier: next QK, this AV, prefetch ---
            if (it + 1 < NIT) {
                zero_acc(cn);
                qk_issue(cn, kB[(it + 1) & 3]);
            }
            const uint32_t pb = smb + 2u * pH;
            const uint32_t vb = vB[it & 3];
#pragma unroll
            for (int kk = 0; kk < 4; ++kk) {
                uint32_t a0[4], a1[4];
                ldsm4(a0[0], a0[1], a0[2], a0[3],
                      pb + (uint32_t)wq * 144u + pa_off + kk * 32u);
                ldsm4(a1[0], a1[1], a1[2], a1[3],
                      pb + (uint32_t)(wq + 16) * 144u + pa_off + kk * 32u);
#pragma unroll
                for (int j2 = 0; j2 < 4; j2 += 2) {
                    uint32_t b0, b1, b2_, b3_;
                    ldsm4t(b0, b1, b2_, b3_, vb + kk * 2304u + va_off + j2 * 16u);
                    mma16(o[0][j2], a0, b0, b1);
                    mma16(o[1][j2], a1, b0, b1);
                    mma16(o[0][j2 + 1], a0, b2_, b3_);
                    mma16(o[1][j2 + 1], a1, b2_, b3_);
                }
            }
            if (it + 2 < NIT) {
                ldg64(Kb, (it + 2) * TN, kr);
                ldg64(Vb, (it + 2) * TN, vr);
            }
        };
        for (int it = 0; it < NIT; it += 2) {
            bodyB(it, cA, cB_);
            bodyB(it + 1, cB_, cA);
        }
    }

    // ---- epilogue: write out [B,S,64] ----
#pragma unroll
    for (int i = 0; i < 2; ++i) {
        const int row = q0 + wq + i * 16 + g;
        float* orow = outp + ((size_t)b * SEQ + row) * HD;
#pragma unroll
        for (int j = 0; j < 4; ++j) {
            const int col = wn + j * 8 + 2 * tg;
            *reinterpret_cast<float2*>(orow + col) = make_float2(o[i][j][0], o[i][j][1]);
            *reinterpret_cast<float2*>(orow + 8 * HD + col) =
                make_float2(o[i][j][2], o[i][j][3]);
        }
    }
}

extern "C" void kernel_launch(void* const* d_in, const int* in_sizes, int n_in,
                              void* d_out, int out_size) {
    const float* q = (const float*)d_in[0];
    const float* k = (const float*)d_in[1];
    const float* v = (const float*)d_in[2];
    float* outp = (float*)d_out;
    float* attnp = outp + (size_t)NBATCH * SEQ * HD;

    cudaFuncSetAttribute(attn_fused, cudaFuncAttributeMaxDynamicSharedMemorySize,
                         SMEM_BYTES);
    attn_fused<<<NBATCH * 32, NTH, SMEM_BYTES>>>(q, k, v, outp, attnp);
}

// round 8
// speedup vs baseline: 1.6129x; 1.0393x over previous
#include <cuda_runtime.h>
#include <cuda_fp16.h>
#include <cstdint>

#define SEQ 4096
#define HD 64
#define NBATCH 4
#define TQ 128
#define TN 128
#define NIT 32
#define NTH 256
#define CEXP 0.18033688011112042f  // log2(e)/temperature(8)

// padded smem strides (in halves)
#define KSTR 72    // K/V tiles: 64 cols -> 144B rows
#define PSTR 136   // P tile: 128 cols -> 272B rows

// smem half-offsets
#define H_P0 0               // P buf 0 (Q staged here in prologue): 128*136 = 17408
#define H_P1 17408           // P buf 1
#define H_K 34816            // 4 rings of 128*72 = 9216
#define H_V 71680            // 4 rings of 9216
#define H_TOT 108544
#define SMEM_BYTES (H_TOT * 2 + 128 * 4)  // + RS

__device__ __half g_QH[NBATCH * SEQ * HD];
__device__ __half g_KH[NBATCH * SEQ * HD];
__device__ __half g_VH[NBATCH * SEQ * HD];

__device__ __forceinline__ uint32_t f2h2(float x, float y) {
    __half2 h = __floats2half2_rn(x, y);
    return *reinterpret_cast<uint32_t*>(&h);
}
__device__ __forceinline__ void ldsm4(uint32_t& r0, uint32_t& r1, uint32_t& r2,
                                      uint32_t& r3, uint32_t addr) {
    asm volatile("ldmatrix.sync.aligned.m8n8.x4.shared.b16 {%0,%1,%2,%3}, [%4];"
                 : "=r"(r0), "=r"(r1), "=r"(r2), "=r"(r3) : "r"(addr));
}
__device__ __forceinline__ void ldsm4t(uint32_t& r0, uint32_t& r1, uint32_t& r2,
                                       uint32_t& r3, uint32_t addr) {
    asm volatile("ldmatrix.sync.aligned.m8n8.x4.trans.shared.b16 {%0,%1,%2,%3}, [%4];"
                 : "=r"(r0), "=r"(r1), "=r"(r2), "=r"(r3) : "r"(addr));
}
__device__ __forceinline__ void mma16(float c[4], const uint32_t a[4], uint32_t b0,
                                      uint32_t b1) {
    asm volatile(
        "mma.sync.aligned.m16n8k16.row.col.f32.f16.f16.f32 "
        "{%0,%1,%2,%3}, {%4,%5,%6,%7}, {%8,%9}, {%0,%1,%2,%3};\n"
        : "+f"(c[0]), "+f"(c[1]), "+f"(c[2]), "+f"(c[3])
        : "r"(a[0]), "r"(a[1]), "r"(a[2]), "r"(a[3]), "r"(b0), "r"(b1));
}
__device__ __forceinline__ void mma16_z(float d[4], const uint32_t a[4], uint32_t b0,
                                        uint32_t b1) {
    asm volatile(
        "mma.sync.aligned.m16n8k16.row.col.f32.f16.f16.f32 "
        "{%0,%1,%2,%3}, {%4,%5,%6,%7}, {%8,%9}, {%10,%10,%10,%10};\n"
        : "=f"(d[0]), "=f"(d[1]), "=f"(d[2]), "=f"(d[3])
        : "r"(a[0]), "r"(a[1]), "r"(a[2]), "r"(a[3]), "r"(b0), "r"(b1), "f"(0.f));
}
__device__ __forceinline__ void cpa16(uint32_t dst, const __half* src) {
    asm volatile("cp.async.cg.shared.global [%0], [%1], 16;" ::"r"(dst), "l"(src));
}
#define CP_COMMIT() asm volatile("cp.async.commit_group;" ::: "memory")
#define CP_WAIT(n) asm volatile("cp.async.wait_group %0;" ::"n"(n) : "memory")

// ---- pre-pass: fp32 -> fp16 for Q, K, V ----
__global__ void __launch_bounds__(256) cvt_kernel(const float* __restrict__ q,
                                                  const float* __restrict__ k,
                                                  const float* __restrict__ v) {
    int i = (blockIdx.x * 256 + threadIdx.x) * 4;
    float4 a = *reinterpret_cast<const float4*>(q + i);
    float4 bk = *reinterpret_cast<const float4*>(k + i);
    float4 c = *reinterpret_cast<const float4*>(v + i);
    *reinterpret_cast<uint2*>(&g_QH[i]) = make_uint2(f2h2(a.x, a.y), f2h2(a.z, a.w));
    *reinterpret_cast<uint2*>(&g_KH[i]) = make_uint2(f2h2(bk.x, bk.y), f2h2(bk.z, bk.w));
    *reinterpret_cast<uint2*>(&g_VH[i]) = make_uint2(f2h2(c.x, c.y), f2h2(c.z, c.w));
}

__global__ void __launch_bounds__(NTH, 1)
attn_fused(float* __restrict__ outp, float* __restrict__ attnp) {
    extern __shared__ __half sh[];
    float* RS = reinterpret_cast<float*>(sh + H_TOT);
    const uint32_t smb = (uint32_t)__cvta_generic_to_shared(sh);

    const int tid = threadIdx.x, w = tid >> 5, lane = tid & 31;
    const int g = lane >> 2, tg = lane & 3;
    const int lr3 = lane & 7, b3 = (lane >> 3) & 1, b4 = (lane >> 4) & 1;
    const int b = blockIdx.x >> 5;
    const int q0 = (blockIdx.x & 31) << 7;
    const int wq = (w >> 1) * 32;
    const int wnq = (w & 1) * 64;   // QK n-slice (64 wide)
    const int wno = (w & 1) * 32;   // AV o n-slice (32 wide)

    // ldmatrix per-thread offsets (bytes)
    const uint32_t kq_off = (uint32_t)(wnq + b4 * 8 + lr3) * 144u + (uint32_t)b3 * 16u;
    const uint32_t pa72 = (uint32_t)(b3 * 8 + lr3) * 144u + (uint32_t)b4 * 16u;   // Q (144B rows)
    const uint32_t pa_off = (uint32_t)(b3 * 8 + lr3) * 272u + (uint32_t)b4 * 16u; // P (272B rows)
    const uint32_t va_off = (uint32_t)(b3 * 8 + lr3) * 144u + (uint32_t)b4 * 16u +
                            (uint32_t)wno * 2u;

    const __half* Qh = g_QH + ((size_t)b * SEQ + q0) * HD;
    const __half* Kh = g_KH + (size_t)b * SEQ * HD;
    const __half* Vh = g_VH + (size_t)b * SEQ * HD;

    if (tid < TQ) RS[tid] = 0.f;

    // stage a 128x64 fp16 tile via cp.async (1024 16B chunks)
    auto stage = [&](uint32_t hbase, const __half* gsrc) {
#pragma unroll
        for (int t = 0; t < 4; ++t) {
            int ci = tid + t * NTH;
            int row = ci >> 3, c8 = ci & 7;
            cpa16(smb + 2u * (uint32_t)(hbase + row * KSTR) + (uint32_t)c8 * 16u,
                  gsrc + row * HD + c8 * 8);
        }
    };

    const uint32_t kB[4] = {smb + 2u * (H_K + 0 * 9216), smb + 2u * (H_K + 1 * 9216),
                            smb + 2u * (H_K + 2 * 9216), smb + 2u * (H_K + 3 * 9216)};
    const uint32_t vB[4] = {smb + 2u * (H_V + 0 * 9216), smb + 2u * (H_V + 1 * 9216),
                            smb + 2u * (H_V + 2 * 9216), smb + 2u * (H_V + 3 * 9216)};

    // ---- prologue: Q + first K tiles ----
    stage(H_P0, Qh);
    CP_COMMIT();
    stage(H_K + 0 * 9216, Kh);
    CP_COMMIT();
    stage(H_K + 1 * 9216, Kh + TN * HD);
    CP_COMMIT();
    CP_WAIT(0);
    __syncthreads();

    // hoist Q fragments (Q staged with 144B rows in P0 region)
    uint32_t qf[4][2][4];
#pragma unroll
    for (int kk = 0; kk < 4; ++kk)
#pragma unroll
        for (int i = 0; i < 2; ++i)
            ldsm4(qf[kk][i][0], qf[kk][i][1], qf[kk][i][2], qf[kk][i][3],
                  smb + (uint32_t)(wq + i * 16) * 144u + pa72 + kk * 32u);

    float c[2][8][4];
    auto qk_issue = [&](uint32_t kbuf) {
#pragma unroll
        for (int kk = 0; kk < 4; ++kk) {
#pragma unroll
            for (int j2 = 0; j2 < 8; j2 += 2) {
                uint32_t b0, b1, b2_, b3_;
                ldsm4(b0, b1, b2_, b3_, kbuf + kq_off + (uint32_t)j2 * 1152u + kk * 32u);
                if (kk == 0) {
                    mma16_z(c[0][j2], qf[0][0], b0, b1);
                    mma16_z(c[1][j2], qf[0][1], b0, b1);
                    mma16_z(c[0][j2 + 1], qf[0][0], b2_, b3_);
                    mma16_z(c[1][j2 + 1], qf[0][1], b2_, b3_);
                } else {
                    mma16(c[0][j2], qf[kk][0], b0, b1);
                    mma16(c[1][j2], qf[kk][1], b0, b1);
                    mma16(c[0][j2 + 1], qf[kk][0], b2_, b3_);
                    mma16(c[1][j2 + 1], qf[kk][1], b2_, b3_);
                }
            }
        }
    };

    // ================= Phase A: rowsums of exp =================
    float rsum[2][2] = {{0.f, 0.f}, {0.f, 0.f}};
    qk_issue(kB[0]);
    for (int it = 0; it < NIT; ++it) {
        if (it + 2 < NIT) {
            stage(H_K + ((it + 2) & 3) * 9216, Kh + (it + 2) * TN * HD);
            CP_COMMIT();
        }
#pragma unroll
        for (int i = 0; i < 2; ++i)
#pragma unroll
            for (int j = 0; j < 8; ++j) {
                rsum[i][0] += exp2f(c[i][j][0] * CEXP) + exp2f(c[i][j][1] * CEXP);
                rsum[i][1] += exp2f(c[i][j][2] * CEXP) + exp2f(c[i][j][3] * CEXP);
            }
        if (it + 2 < NIT) CP_WAIT(1); else CP_WAIT(0);
        __syncthreads();
        if (it + 1 < NIT) qk_issue(kB[(it + 1) & 3]);
    }
#pragma unroll
    for (int i = 0; i < 2; ++i)
#pragma unroll
        for (int h = 0; h < 2; ++h) {
            float v = rsum[i][h];
            v += __shfl_xor_sync(0xffffffffu, v, 1);
            v += __shfl_xor_sync(0xffffffffu, v, 2);
            if (tg == 0) atomicAdd(&RS[wq + i * 16 + h * 8 + g], v);
        }
    __syncthreads();
    float lr[2][2];
#pragma unroll
    for (int i = 0; i < 2; ++i)
#pragma unroll
        for (int h = 0; h < 2; ++h) lr[i][h] = -log2f(RS[wq + i * 16 + h * 8 + g]);

    // ================= Phase B: attn + AV =================
    float o[2][4][4] = {};
    __syncthreads();
    stage(H_K + 0 * 9216, Kh);
    stage(H_V + 0 * 9216, Vh);
    CP_COMMIT();
    stage(H_K + 1 * 9216, Kh + TN * HD);
    stage(H_V + 1 * 9216, Vh + TN * HD);
    CP_COMMIT();
    CP_WAIT(0);
    __syncthreads();
    qk_issue(kB[0]);

    for (int it = 0; it < NIT; ++it) {
        const int n0 = it * TN;
        // --- pre-barrier: stage(it+2), exp + attn STG + P STS ---
        if (it + 2 < NIT) {
            stage(H_K + ((it + 2) & 3) * 9216, Kh + (it + 2) * TN * HD);
            stage(H_V + ((it + 2) & 3) * 9216, Vh + (it + 2) * TN * HD);
            CP_COMMIT();
        }
        const uint32_t pH = (it & 1) ? H_P1 : H_P0;
#pragma unroll
        for (int i = 0; i < 2; ++i) {
            const int r = wq + i * 16 + g;
            const int row = q0 + r;
            float* ar = attnp + ((size_t)b * SEQ + row) * SEQ + n0 + wnq;
#pragma unroll
            for (int j = 0; j < 8; ++j) {
                c[i][j][0] = exp2f(fmaf(c[i][j][0], CEXP, lr[i][0]));
                c[i][j][1] = exp2f(fmaf(c[i][j][1], CEXP, lr[i][0]));
                c[i][j][2] = exp2f(fmaf(c[i][j][2], CEXP, lr[i][1]));
                c[i][j][3] = exp2f(fmaf(c[i][j][3], CEXP, lr[i][1]));
                __stcs(reinterpret_cast<float2*>(ar + j * 8 + 2 * tg),
                       make_float2(c[i][j][0], c[i][j][1]));
                __stcs(reinterpret_cast<float2*>(ar + (size_t)8 * SEQ + j * 8 + 2 * tg),
                       make_float2(c[i][j][2], c[i][j][3]));
                const int col = wnq + j * 8 + 2 * tg;
                *reinterpret_cast<uint32_t*>(&sh[pH + r * PSTR + col]) =
                    f2h2(c[i][j][0], c[i][j][1]);
                *reinterpret_cast<uint32_t*>(&sh[pH + (r + 8) * PSTR + col]) =
                    f2h2(c[i][j][2], c[i][j][3]);
            }
        }
        if (it + 2 < NIT) CP_WAIT(1); else CP_WAIT(0);
        __syncthreads();
        // --- post-barrier: next QK, this AV ---
        if (it + 1 < NIT) qk_issue(kB[(it + 1) & 3]);
        const uint32_t pb = smb + 2u * pH;
        const uint32_t vb = vB[it & 3];
#pragma unroll
        for (int kk = 0; kk < 8; ++kk) {
            uint32_t a0[4], a1[4];
            ldsm4(a0[0], a0[1], a0[2], a0[3],
                  pb + (uint32_t)wq * 272u + pa_off + kk * 32u);
            ldsm4(a1[0], a1[1], a1[2], a1[3],
                  pb + (uint32_t)(wq + 16) * 272u + pa_off + kk * 32u);
#pragma unroll
            for (int j2 = 0; j2 < 4; j2 += 2) {
                uint32_t b0, b1, b2_, b3_;
                ldsm4t(b0, b1, b2_, b3_, vb + kk * 2304u + va_off + j2 * 16u);
                mma16(o[0][j2], a0, b0, b1);
                mma16(o[1][j2], a1, b0, b1);
                mma16(o[0][j2 + 1], a0, b2_, b3_);
                mma16(o[1][j2 + 1], a1, b2_, b3_);
            }
        }
    }

    // ---- epilogue: write out [B,S,64] ----
#pragma unroll
    for (int i = 0; i < 2; ++i) {
        const int row = q0 + wq + i * 16 + g;
        float* orow = outp + ((size_t)b * SEQ + row) * HD;
#pragma unroll
        for (int j = 0; j < 4; ++j) {
            const int col = wno + j * 8 + 2 * tg;
            *reinterpret_cast<float2*>(orow + col) = make_float2(o[i][j][0], o[i][j][1]);
            *reinterpret_cast<float2*>(orow + 8 * HD + col) =
                make_float2(o[i][j][2], o[i][j][3]);
        }
    }
}

extern "C" void kernel_launch(void* const* d_in, const int* in_sizes, int n_in,
                              void* d_out, int out_size) {
    const float* q = (const float*)d_in[0];
    const float* k = (const float*)d_in[1];
    const float* v = (const float*)d_in[2];
    float* outp = (float*)d_out;
    float* attnp = outp + (size_t)NBATCH * SEQ * HD;

    cvt_kernel<<<NBATCH * SEQ * HD / (256 * 4), 256>>>(q, k, v);

    cudaFuncSetAttribute(attn_fused, cudaFuncAttributeMaxDynamicSharedMemorySize,
                         SMEM_BYTES);
    attn_fused<<<NBATCH * 32, NTH, SMEM_BYTES>>>(outp, attnp);
}